// round 16
// baseline (speedup 1.0000x reference)
#include <cuda_runtime.h>
#include <cstdint>

// ============================================================================
// out[f32,4096x4096] = mat1[i32] @ mat2[i32] + input[i32], values in [0,16)
// s8 path. R16: tensor+dp4a COLUMN-SPLIT hybrid.
//   Evidence: m16n8k32.s8 is hard-capped at ~3.7cyc/MMA/SM (R8/R11/R13/R15 all
//   222us). Only reducing MMA count helps -> offload cols 112..127 to the idle
//   ALU pipe via dp4a, computed by 4 dedicated warps from the same SMEM stages.
// CTA 128x128x128, 256 thr: warps 0-3 tensor (64x56), warps 4-7 dp4a (128x16).
// ============================================================================

#define MSZ 4096
#define BM 128
#define BN 128
#define XT 112                     // tensor columns; dp4a covers BN-XT = 16
#define BK 128
#define STAGES 3
#define NKT (MSZ / BK)             // 32
#define ROWB 144                   // padded SMEM row: 128 data + 16 pad
#define STAGE_A (BM * ROWB)        // 18432
#define STAGE_B (BN * ROWB)        // 18432
#define STAGE_BYTES (STAGE_A + STAGE_B)      // 36864
#define SMEM_DYN (STAGES * STAGE_BYTES)      // 110592

__device__ __align__(128) uint8_t g_packA[(size_t)MSZ * MSZ];   // [M,K] s8
__device__ __align__(128) uint8_t g_packBt[(size_t)MSZ * MSZ];  // [N,K] s8 (B^T)

// ---------------------------------------------------------------- helpers
__device__ __forceinline__ uint32_t smem_u32(const void* p) {
    uint32_t a;
    asm("{ .reg .u64 t; cvta.to.shared.u64 t, %1; cvt.u32.u64 %0, t; }"
        : "=r"(a) : "l"(p));
    return a;
}

#define CPA16(dst, src) \
    asm volatile("cp.async.cg.shared.global [%0], [%1], 16;" :: "r"(dst), "l"(src) : "memory")
#define CPC() asm volatile("cp.async.commit_group;" ::: "memory")
#define CPW(n) asm volatile("cp.async.wait_group %0;" :: "n"(n) : "memory")

#define LDSM4(r0, r1, r2, r3, addr) \
    asm volatile("ldmatrix.sync.aligned.m8n8.x4.shared.b16 {%0,%1,%2,%3}, [%4];" \
                 : "=r"(r0), "=r"(r1), "=r"(r2), "=r"(r3) : "r"(addr))

#define LDSM2(r0, r1, addr) \
    asm volatile("ldmatrix.sync.aligned.m8n8.x2.shared.b16 {%0,%1}, [%2];" \
                 : "=r"(r0), "=r"(r1) : "r"(addr))

#define MMA_S8(d, a, b0, b1) \
    asm volatile("mma.sync.aligned.m16n8k32.row.col.s32.s8.s8.s32 " \
                 "{%0,%1,%2,%3}, {%4,%5,%6,%7}, {%8,%9}, {%0,%1,%2,%3};" \
                 : "+r"((d)[0]), "+r"((d)[1]), "+r"((d)[2]), "+r"((d)[3]) \
                 : "r"((a)[0]), "r"((a)[1]), "r"((a)[2]), "r"((a)[3]), \
                   "r"(b0), "r"(b1))

#define LDS32(r, addr) \
    asm volatile("ld.shared.b32 %0, [%1];" : "=r"(r) : "r"(addr))

#define DP4A(c, a, b) \
    asm volatile("dp4a.s32.s32 %0, %1, %2, %0;" : "+r"(c) : "r"(a), "r"(b))

// stage loader: 256 threads; A 1024 + B 1024 16B chunks; 8 per thread.
#define LOAD_STAGE(kt, st) do {                                                           \
    const uint32_t sA_ = smbase + (st) * STAGE_BYTES;                                     \
    const uint32_t sB_ = sA_ + STAGE_A;                                                   \
    const uint8_t* pA_ = g_packA  + (size_t)m0 * MSZ + (size_t)(kt) * BK;                 \
    const uint8_t* pB_ = g_packBt + (size_t)n0 * MSZ + (size_t)(kt) * BK;                 \
    _Pragma("unroll")                                                                     \
    for (int i_ = 0; i_ < 4; i_++) {                                                      \
        const int row_ = ldRow + i_ * 32;                                                 \
        CPA16(sA_ + row_ * ROWB + ldSeg, pA_ + (size_t)row_ * MSZ + ldSeg);               \
        CPA16(sB_ + row_ * ROWB + ldSeg, pB_ + (size_t)row_ * MSZ + ldSeg);               \
    }                                                                                     \
    CPC();                                                                                \
} while (0)

// ---------------------------------------------------------------- fused pack
__global__ void pack_kernel(const int* __restrict__ A, const int* __restrict__ B) {
    if (blockIdx.x < 16384) {
        size_t i = (size_t)blockIdx.x * 256 + threadIdx.x;
        int4 v = ((const int4*)A)[i];
        uchar4 r;
        r.x = (uint8_t)v.x; r.y = (uint8_t)v.y; r.z = (uint8_t)v.z; r.w = (uint8_t)v.w;
        ((uchar4*)g_packA)[i] = r;
    } else {
        __shared__ uint8_t tsm[32][132];
        const int b2 = blockIdx.x - 16384;
        const int kb = (b2 & 31) * 128;
        const int nb = (b2 >> 5) * 32;
        const int t = threadIdx.x;
        const int kloc = t >> 5;
        const int nloc = t & 31;
        #pragma unroll
        for (int i = 0; i < 16; i++) {
            int k = kloc + i * 8;
            tsm[nloc][k] = (uint8_t)B[(size_t)(kb + k) * MSZ + nb + nloc];
        }
        __syncthreads();
        const int k4 = (t & 31) * 4;
        const int nrow = t >> 5;
        #pragma unroll
        for (int i = 0; i < 4; i++) {
            int n = nrow + i * 8;
            uchar4 v;
            v.x = tsm[n][k4]; v.y = tsm[n][k4 + 1]; v.z = tsm[n][k4 + 2]; v.w = tsm[n][k4 + 3];
            *(uchar4*)&g_packBt[(size_t)(nb + n) * MSZ + kb + k4] = v;
        }
    }
}

// ---------------------------------------------------------------- GEMM
// 256 threads: warps 0-3 tensor 2(m)x2(n) of 64x56; warps 4-7 dp4a 128x16.
__global__ void __launch_bounds__(256, 1)
gemm_kernel(const int* __restrict__ gIn, float* __restrict__ gOut) {
    extern __shared__ uint8_t dsm[];
    const uint32_t smbase = smem_u32(dsm);

    const int tid = threadIdx.x;
    const int l = tid & 31;
    const int warp = tid >> 5;
    const int m0 = blockIdx.y * BM;
    const int n0 = blockIdx.x * BN;

    const int ldRow = tid >> 3 & 31;     // 0..31
    const int ldSeg = (tid & 7) * 16;    // 0..112

    LOAD_STAGE(0, 0);
    LOAD_STAGE(1, 1);

    if (warp < 4) {
        // ---------------- tensor warps: 64x56 tile at (wm*64, wn*56)
        const int wm = warp >> 1;
        const int wn = warp & 1;
        const int aRowL = (l & 7) + ((l >> 3) & 1) * 8;
        const int aChk  = ((l >> 4) & 1) * 16;
        const int bRowL = (l & 7) + ((l >> 4) & 1) * 8;
        const int bChk  = ((l >> 3) & 1) * 16;
        const int bRowL2 = (l & 7);
        const int bChk2  = ((l >> 3) & 1) * 16;

        int acc[4][7][4];
        #pragma unroll
        for (int mi = 0; mi < 4; mi++)
            #pragma unroll
            for (int ni = 0; ni < 7; ni++)
                #pragma unroll
                for (int r = 0; r < 4; r++) acc[mi][ni][r] = 0;

        for (int kt = 0; kt < NKT; kt++) {
            CPW(STAGES - 2);
            __syncthreads();
            if (kt + STAGES - 1 < NKT) { LOAD_STAGE(kt + STAGES - 1, (kt + STAGES - 1) % STAGES); }
            else { CPC(); }

            const uint32_t sA = smbase + (kt % STAGES) * STAGE_BYTES;
            const uint32_t sB = sA + STAGE_A;

            #pragma unroll
            for (int ks = 0; ks < 4; ks++) {
                const uint32_t ko = (uint32_t)ks * 32;
                uint32_t a[4][4];
                #pragma unroll
                for (int mi = 0; mi < 4; mi++) {
                    uint32_t addr = sA + (uint32_t)(wm * 64 + mi * 16 + aRowL) * ROWB
                                  + aChk + ko;
                    LDSM4(a[mi][0], a[mi][1], a[mi][2], a[mi][3], addr);
                }
                #pragma unroll
                for (int np = 0; np < 3; np++) {
                    uint32_t r0, r1, r2, r3;
                    uint32_t addr = sB + (uint32_t)(wn * 56 + np * 16 + bRowL) * ROWB
                                  + bChk + ko;
                    LDSM4(r0, r1, r2, r3, addr);
                    #pragma unroll
                    for (int mi = 0; mi < 4; mi++) {
                        MMA_S8(acc[mi][np * 2 + 0], a[mi], r0, r1);
                        MMA_S8(acc[mi][np * 2 + 1], a[mi], r2, r3);
                    }
                }
                {
                    uint32_t r0, r1;
                    uint32_t addr = sB + (uint32_t)(wn * 56 + 48 + bRowL2) * ROWB
                                  + bChk2 + ko;
                    LDSM2(r0, r1, addr);
                    #pragma unroll
                    for (int mi = 0; mi < 4; mi++)
                        MMA_S8(acc[mi][6], a[mi], r0, r1);
                }
            }
        }

        // tensor epilogue: cols n0 + wn*56 + ni*8 + ccol
        const int crow = l >> 2;
        const int ccol = (l & 3) * 2;
        #pragma unroll
        for (int mi = 0; mi < 4; mi++) {
            #pragma unroll
            for (int ni = 0; ni < 7; ni++) {
                const int row = m0 + wm * 64 + mi * 16 + crow;
                const int col = n0 + wn * 56 + ni * 8 + ccol;
                const size_t gi = (size_t)row * MSZ + col;
                const int2 in0 = *(const int2*)&gIn[gi];
                const int2 in1 = *(const int2*)&gIn[gi + (size_t)8 * MSZ];
                float2 o0, o1;
                o0.x = (float)(acc[mi][ni][0] + in0.x);
                o0.y = (float)(acc[mi][ni][1] + in0.y);
                o1.x = (float)(acc[mi][ni][2] + in1.x);
                o1.y = (float)(acc[mi][ni][3] + in1.y);
                *(float2*)&gOut[gi] = o0;
                *(float2*)&gOut[gi + (size_t)8 * MSZ] = o1;
            }
        }
    } else {
        // ---------------- dp4a warps: cols 112..127, rows (warp-4)*32..+31
        const int w = warp - 4;
        const int r0base = w * 32 + (l >> 2) * 4;   // 4 rows per thread
        const int c0base = XT + (l & 3) * 4;        // 4 cols per thread

        int c[4][4];
        #pragma unroll
        for (int i = 0; i < 4; i++)
            #pragma unroll
            for (int j = 0; j < 4; j++) c[i][j] = 0;

        for (int kt = 0; kt < NKT; kt++) {
            CPW(STAGES - 2);
            __syncthreads();
            if (kt + STAGES - 1 < NKT) { LOAD_STAGE(kt + STAGES - 1, (kt + STAGES - 1) % STAGES); }
            else { CPC(); }

            const uint32_t sA = smbase + (kt % STAGES) * STAGE_BYTES;
            const uint32_t sB = sA + STAGE_A;
            const uint32_t aBase = sA + (uint32_t)r0base * ROWB;
            const uint32_t bBase = sB + (uint32_t)c0base * ROWB;

            #pragma unroll 8
            for (int ch = 0; ch < 32; ch++) {
                const uint32_t ko = (uint32_t)ch * 4;
                uint32_t av[4], bv[4];
                #pragma unroll
                for (int i = 0; i < 4; i++) LDS32(av[i], aBase + i * ROWB + ko);
                #pragma unroll
                for (int j = 0; j < 4; j++) LDS32(bv[j], bBase + j * ROWB + ko);
                #pragma unroll
                for (int i = 0; i < 4; i++)
                    #pragma unroll
                    for (int j = 0; j < 4; j++)
                        DP4A(c[i][j], av[i], bv[j]);
            }
        }

        // dp4a epilogue: float4 stores, cols contiguous
        #pragma unroll
        for (int i = 0; i < 4; i++) {
            const int row = m0 + r0base + i;
            const int col = n0 + c0base;
            const size_t gi = (size_t)row * MSZ + col;
            const int4 iv = *(const int4*)&gIn[gi];
            float4 ov;
            ov.x = (float)(c[i][0] + iv.x);
            ov.y = (float)(c[i][1] + iv.y);
            ov.z = (float)(c[i][2] + iv.z);
            ov.w = (float)(c[i][3] + iv.w);
            *(float4*)&gOut[gi] = ov;
        }
    }
}

// ---------------------------------------------------------------- launch
extern "C" void kernel_launch(void* const* d_in, const int* in_sizes, int n_in,
                              void* d_out, int out_size) {
    const int* inp  = (const int*)d_in[0];   // input_tensor [M,N]
    const int* mat1 = (const int*)d_in[1];   // [M,K]
    const int* mat2 = (const int*)d_in[2];   // [K,N]
    float* out = (float*)d_out;

    pack_kernel<<<16384 + 4096, 256>>>(mat1, mat2);

    static int smem_set = 0;
    if (!smem_set) {
        cudaFuncSetAttribute(gemm_kernel, cudaFuncAttributeMaxDynamicSharedMemorySize, SMEM_DYN);
        smem_set = 1;
    }
    gemm_kernel<<<dim3(MSZ / BN, MSZ / BM), 256, SMEM_DYN>>>(inp, out);
}